// round 2
// baseline (speedup 1.0000x reference)
#include <cuda_runtime.h>
#include <math.h>

// ---------------- problem constants ----------------
#define NND   50000    // nodes
#define FINN  100      // input feature dim
#define NHID  100      // per-head hidden
#define EE    800000   // edges
#define NREL  200      // relations
#define BATCH 512
#define HD    100      // HDIM
#define D2    200      // H*NHID

// ---------------- device scratch (sanctioned __device__ globals) ----------------
__device__ int g_cnt[NND];
__device__ int g_cur[NND];
__device__ int g_rowptr[NND + 1];
__device__ int g_mask[NND];
__device__ int g_need1[NND];
__device__ int g_csr_e1[EE];
__device__ int g_csr_t[EE];
__device__ int g_t2map[NREL];

__device__ float g_vs1[2 * FINN], g_vd1[2 * FINN], g_vr1[2 * FINN];
__device__ float g_vs2[D2], g_vd2[D2], g_vr2[D2];
__device__ float g_rp1[2 * NREL * NHID];
__device__ float g_pr1[2 * NREL];
__device__ float g_RT2[NREL * D2];
__device__ float g_rp2[NREL * D2];   // pre-composed with t2map
__device__ float g_pr2[NREL];        // pre-composed with t2map
__device__ float g_he[BATCH * HD];

__device__ float g_xn[NND * FINN];
__device__ float g_ps1[2 * NND], g_pd1[2 * NND];
__device__ float g_xd1[2 * NND * NHID];
__device__ float g_xs1[2 * NND * NHID];
__device__ float g_x1[NND * D2];
__device__ float g_xd2[NND * D2], g_xs2[NND * D2];
__device__ float g_ps2[NND], g_pd2[NND];
__device__ float g_x2[NND * D2];
__device__ float g_eu[NND * D2];

// ---------------- small helpers ----------------
__device__ __forceinline__ float lrelu_neg(float z) {
    // returns -leaky_relu(z, 0.2)
    return (z >= 0.f) ? -z : -0.2f * z;
}

// ---------------- kernels ----------------

// zero cnt, cur, mask, need1
__global__ void k_clear() {
    int i = blockIdx.x * blockDim.x + threadIdx.x;
    int stride = gridDim.x * blockDim.x;
    for (int idx = i; idx < 4 * NND; idx += stride) {
        int which = idx / NND, j = idx % NND;
        if (which == 0) g_cnt[j] = 0;
        else if (which == 1) g_cur[j] = 0;
        else if (which == 2) g_mask[j] = 0;
        else g_need1[j] = 0;
    }
}

// set mask + seed need1 from batch_inputs[:,2]
__global__ void k_mask(const int* __restrict__ bi) {
    int b = threadIdx.x;
    if (b < BATCH) {
        int node = bi[b * 4 + 2];
        g_mask[node] = 1;
        g_need1[node] = 1;
    }
}

// small precomputes: he table, t2map, combined logit vectors
__global__ void k_pre_small(const int* __restrict__ bi,
                            const float* __restrict__ wt2,
                            const float* __restrict__ bt2,
                            const int* __restrict__ etype,
                            const float* __restrict__ a_h,
                            const float* __restrict__ a2_h,
                            const float* __restrict__ a_o,
                            const float* __restrict__ a2_o) {
    int blk = blockIdx.x;
    int tid = threadIdx.x;  // 256
    if (blk < BATCH) {
        // he[b, d] = cos(t * w[d] + b[d]) — match mul-then-add fp32 rounding,
        // cosine in double (safe for huge args regardless of fast-math)
        if (tid < HD) {
            float tf = (float)bi[blk * 4 + 3];
            float arg = __fadd_rn(__fmul_rn(tf, wt2[tid]), bt2[tid]);
            g_he[blk * HD + tid] = (float)cos((double)arg);
        }
    } else if (blk == BATCH) {
        if (tid < NREL) g_t2map[tid] = etype[tid];
    } else if (blk == BATCH + 1 || blk == BATCH + 2) {
        int h = blk - (BATCH + 1);
        if (tid < FINN) {
            float s0 = 0.f, s1 = 0.f, s2 = 0.f;
            for (int o = 0; o < NHID; o++) {
                float a2v = a2_h[h * NHID + o];
                const float* row = a_h + (size_t)h * NHID * 300 + (size_t)o * 300;
                s0 += row[tid] * a2v;            // a_src
                s1 += row[100 + tid] * a2v;      // a_dst
                s2 += row[200 + tid] * a2v;      // a_rel
            }
            g_vs1[h * FINN + tid] = s0;
            g_vd1[h * FINN + tid] = s1;
            g_vr1[h * FINN + tid] = s2;
        }
    } else if (blk == BATCH + 3) {
        if (tid < D2) {
            float s0 = 0.f, s1 = 0.f, s2 = 0.f;
            for (int o = 0; o < D2; o++) {
                float a2v = a2_o[o];
                const float* row = a_o + (size_t)o * 600;
                s0 += row[tid] * a2v;
                s1 += row[200 + tid] * a2v;
                s2 += row[400 + tid] * a2v;
            }
            g_vs2[tid] = s0;
            g_vd2[tid] = s1;
            g_vr2[tid] = s2;
        }
    }
}

// rp1 (2x200x100), RT2 (200x200), pr1 (2x200)
__global__ void k_pre_mats(const float* __restrict__ rel,
                           const float* __restrict__ a_h,
                           const float* __restrict__ W_rel) {
    int idx = blockIdx.x * blockDim.x + threadIdx.x;
    if (idx < 2 * NREL * NHID) {
        int h = idx / (NREL * NHID);
        int r = idx % (NREL * NHID);
        int t = r / NHID, o = r % NHID;
        const float* rrow = rel + (size_t)t * 100;
        const float* arow = a_h + (size_t)h * NHID * 300 + (size_t)o * 300 + 200;
        float s = 0.f;
        for (int k = 0; k < 100; k++) s += rrow[k] * arow[k];
        g_rp1[idx] = s;
    } else if (idx < 2 * NREL * NHID + NREL * D2) {
        int j = idx - 2 * NREL * NHID;
        int t = j / D2, k = j % D2;
        const float* rrow = rel + (size_t)t * 100;
        float s = 0.f;
        for (int r = 0; r < 100; r++) s += rrow[r] * W_rel[r * D2 + k];
        g_RT2[t * D2 + k] = s;
    } else if (idx < 2 * NREL * NHID + NREL * D2 + 2 * NREL) {
        int j = idx - (2 * NREL * NHID + NREL * D2);
        int h = j / NREL, t = j % NREL;
        const float* rrow = rel + (size_t)t * 100;
        float s = 0.f;
        for (int r = 0; r < 100; r++) s += rrow[r] * g_vr1[h * FINN + r];
        g_pr1[h * NREL + t] = s;
    }
}

// rp2 (composed with t2map), pr2
__global__ void k_pre2(const float* __restrict__ a_o) {
    int idx = blockIdx.x * blockDim.x + threadIdx.x;
    if (idx < NREL * D2) {
        int t = idx / D2, o = idx % D2;
        int s2 = g_t2map[t];
        const float* rrow = g_RT2 + (size_t)s2 * D2;
        const float* arow = a_o + (size_t)o * 600 + 400;
        float s = 0.f;
        for (int k = 0; k < D2; k++) s += rrow[k] * arow[k];
        g_rp2[t * D2 + o] = s;
    } else if (idx < NREL * D2 + NREL) {
        int t = idx - NREL * D2;
        int s2 = g_t2map[t];
        const float* rrow = g_RT2 + (size_t)s2 * D2;
        float s = 0.f;
        for (int k = 0; k < D2; k++) s += rrow[k] * g_vr2[k];
        g_pr2[t] = s;
    }
}

// histogram of edge0 + need1 flags for neighbors of masked nodes
__global__ void k_hist_flags(const int* __restrict__ el) {
    int e = blockIdx.x * blockDim.x + threadIdx.x;
    if (e >= EE) return;
    int e0 = el[e];
    int e1 = el[EE + e];
    atomicAdd(&g_cnt[e0], 1);
    if (g_mask[e0]) g_need1[e1] = 1;
}

// single-block exclusive scan of g_cnt -> g_rowptr
__global__ void k_scan() {
    __shared__ int sm[1024];
    int t = threadIdx.x;
    const int CH = 49;  // 1024*49 = 50176 >= 50000
    int base = t * CH;
    int s = 0;
    for (int i = 0; i < CH; i++) {
        int idx = base + i;
        if (idx < NND) s += g_cnt[idx];
    }
    sm[t] = s;
    __syncthreads();
    for (int off = 1; off < 1024; off <<= 1) {
        int v = 0;
        if (t >= off) v = sm[t - off];
        __syncthreads();
        if (t >= off) sm[t] += v;
        __syncthreads();
    }
    int run = (t == 0) ? 0 : sm[t - 1];
    for (int i = 0; i < CH; i++) {
        int idx = base + i;
        if (idx < NND) {
            g_rowptr[idx] = run;
            run += g_cnt[idx];
        }
    }
    if (t == 1023) g_rowptr[NND] = run;
}

// scatter edges into CSR slots
__global__ void k_scatter(const int* __restrict__ el, const int* __restrict__ etype) {
    int e = blockIdx.x * blockDim.x + threadIdx.x;
    if (e >= EE) return;
    int e0 = el[e];
    int pos = g_rowptr[e0] + atomicAdd(&g_cur[e0], 1);
    g_csr_e1[pos] = el[EE + e];
    g_csr_t[pos] = etype[e];
}

// row-normalize entity embeddings (for final projection)
__global__ void k_xn(const float* __restrict__ x) {
    int warp = (blockIdx.x * blockDim.x + threadIdx.x) >> 5;
    int lane = threadIdx.x & 31;
    if (warp >= NND) return;
    const float* row = x + (size_t)warp * FINN;
    float ss = 0.f;
    for (int k = lane; k < FINN; k += 32) { float v = row[k]; ss += v * v; }
    for (int o = 16; o > 0; o >>= 1) ss += __shfl_xor_sync(0xffffffffu, ss, o);
    float scale = 1.f / fmaxf(sqrtf(ss), 1e-12f);
    float* dst = g_xn + (size_t)warp * FINN;
    for (int k = lane; k < FINN; k += 32) dst[k] = row[k] * scale;
}

// per-node logit scalars ps1/pd1 for both heads (all N — cheap matvecs)
__global__ void k_vecs(const float* __restrict__ x) {
    int warp = (blockIdx.x * blockDim.x + threadIdx.x) >> 5;
    int lane = threadIdx.x & 31;
    if (warp >= NND) return;
    const float* row = x + (size_t)warp * FINN;
    float a0 = 0.f, a1 = 0.f, b0 = 0.f, b1 = 0.f;
    for (int k = lane; k < FINN; k += 32) {
        float v = row[k];
        a0 += v * g_vs1[k];
        a1 += v * g_vs1[FINN + k];
        b0 += v * g_vd1[k];
        b1 += v * g_vd1[FINN + k];
    }
    for (int o = 16; o > 0; o >>= 1) {
        a0 += __shfl_xor_sync(0xffffffffu, a0, o);
        a1 += __shfl_xor_sync(0xffffffffu, a1, o);
        b0 += __shfl_xor_sync(0xffffffffu, b0, o);
        b1 += __shfl_xor_sync(0xffffffffu, b1, o);
    }
    if (lane == 0) {
        g_ps1[warp] = a0;
        g_ps1[NND + warp] = a1;
        g_pd1[warp] = b0;
        g_pd1[NND + warp] = b1;
    }
}

// SGEMM: C[M,O] = A[M,K] * op(B); TRANSB=1: B is [O,K] row-major (ldb = row stride)
//                                  TRANSB=0: B is [K,O] row-major
template <int TRANSB>
__global__ void k_gemm(const float* __restrict__ A, const float* __restrict__ B,
                       float* __restrict__ C, int M, int K, int O,
                       int lda, int ldb, int ldc) {
    const int BM = 128, BN = 128, BK = 20;
    __shared__ float As[BK][BM + 4];
    __shared__ float Bs[BK][BN + 4];
    int tid = threadIdx.x;  // 256
    int tx = tid % 16, ty = tid / 16;
    int m0 = blockIdx.x * BM, o0 = blockIdx.y * BN;
    float acc[8][8];
#pragma unroll
    for (int i = 0; i < 8; i++)
#pragma unroll
        for (int j = 0; j < 8; j++) acc[i][j] = 0.f;

    for (int k0 = 0; k0 < K; k0 += BK) {
        for (int i = tid; i < BM * BK; i += 256) {
            int m = i / BK, k = i % BK;
            int gm = m0 + m, gk = k0 + k;
            As[k][m] = (gm < M && gk < K) ? A[(size_t)gm * lda + gk] : 0.f;
        }
        for (int i = tid; i < BN * BK; i += 256) {
            int o, k;
            float v = 0.f;
            if (TRANSB) {
                o = i / BK; k = i % BK;
                int go = o0 + o, gk = k0 + k;
                if (go < O && gk < K) v = B[(size_t)go * ldb + gk];
            } else {
                o = i % BN; k = i / BN;
                int go = o0 + o, gk = k0 + k;
                if (go < O && gk < K) v = B[(size_t)gk * ldb + go];
            }
            Bs[k][o] = v;
        }
        __syncthreads();
#pragma unroll
        for (int kk = 0; kk < BK; kk++) {
            float a[8], b[8];
#pragma unroll
            for (int i = 0; i < 8; i++) { a[i] = As[kk][ty * 8 + i]; b[i] = Bs[kk][tx * 8 + i]; }
#pragma unroll
            for (int i = 0; i < 8; i++)
#pragma unroll
                for (int j = 0; j < 8; j++) acc[i][j] += a[i] * b[j];
        }
        __syncthreads();
    }
#pragma unroll
    for (int i = 0; i < 8; i++) {
        int gm = m0 + ty * 8 + i;
        if (gm >= M) continue;
#pragma unroll
        for (int j = 0; j < 8; j++) {
            int go = o0 + tx * 8 + j;
            if (go < O) C[(size_t)gm * ldc + go] = acc[i][j];
        }
    }
}

// xs1 projection, only at need1 nodes (both heads)
__global__ void k_xs1(const float* __restrict__ x, const float* __restrict__ a_h) {
    int n = blockIdx.x;
    if (!g_need1[n]) return;
    __shared__ float sx[FINN];
    int tid = threadIdx.x;  // 128
    if (tid < FINN) sx[tid] = x[(size_t)n * FINN + tid];
    __syncthreads();
    for (int idx = tid; idx < 2 * NHID; idx += 128) {
        int h = idx / NHID, o = idx % NHID;
        const float* arow = a_h + (size_t)h * NHID * 300 + (size_t)o * 300;
        float s = 0.f;
        for (int k = 0; k < FINN; k++) s += sx[k] * arow[k];
        g_xs1[((size_t)h * NND + n) * NHID + o] = s;
    }
}

// layer-1 aggregation at need1 nodes (both heads), writes x1[n,0:200]
__global__ void k_agg1() {
    int n = blockIdx.x;
    if (!g_need1[n]) return;
    int d = threadIdx.x;  // 128; active for vectors if d<100
    float ps_a = g_ps1[n];
    float ps_b = g_ps1[NND + n];
    int s = g_rowptr[n], e = g_rowptr[n + 1];
    float acc0 = 0.f, acc1 = 0.f, ws0 = 0.f, ws1 = 0.f;
    for (int i = s; i < e; i++) {
        int e1 = g_csr_e1[i];
        int t = g_csr_t[i];
        float z0 = ps_a + g_pd1[e1] + g_pr1[t];
        float z1 = ps_b + g_pd1[NND + e1] + g_pr1[NREL + t];
        float w0 = expf(lrelu_neg(z0));
        float w1 = expf(lrelu_neg(z1));
        ws0 += w0;
        ws1 += w1;
        if (d < NHID) {
            acc0 += w0 * (g_xd1[(size_t)e1 * NHID + d] + g_rp1[(size_t)t * NHID + d]);
            acc1 += w1 * (g_xd1[((size_t)NND + e1) * NHID + d] +
                          g_rp1[((size_t)NREL + t) * NHID + d]);
        }
    }
    if (d < NHID) {
        float h0 = (g_xs1[(size_t)n * NHID + d] * ws0 + acc0) / (ws0 + 1e-12f);
        float h1 = (g_xs1[((size_t)NND + n) * NHID + d] * ws1 + acc1) / (ws1 + 1e-12f);
        g_x1[(size_t)n * D2 + d] = (h0 > 0.f) ? h0 : expm1f(h0);
        g_x1[(size_t)n * D2 + NHID + d] = (h1 > 0.f) ? h1 : expm1f(h1);
    }
}

// layer-2 projections at need1 nodes (xd2/pd2); also xs2/ps2 at mask nodes
__global__ void k_proj2(const float* __restrict__ a_o) {
    int n = blockIdx.x;
    if (!g_need1[n]) return;
    __shared__ float sx[D2];
    __shared__ float red[256];
    int tid = threadIdx.x;  // 256
    if (tid < D2) sx[tid] = g_x1[(size_t)n * D2 + tid];
    __syncthreads();
    int msk = g_mask[n];
    if (tid < D2) {
        const float* ad = a_o + (size_t)tid * 600 + 200;
        float s = 0.f;
        for (int k = 0; k < D2; k++) s += sx[k] * ad[k];
        g_xd2[(size_t)n * D2 + tid] = s;
        if (msk) {
            const float* as2 = a_o + (size_t)tid * 600;
            float s2 = 0.f;
            for (int k = 0; k < D2; k++) s2 += sx[k] * as2[k];
            g_xs2[(size_t)n * D2 + tid] = s2;
        }
    }
    // pd2 reduction
    red[tid] = (tid < D2) ? sx[tid] * g_vd2[tid] : 0.f;
    __syncthreads();
    for (int s = 128; s > 0; s >>= 1) {
        if (tid < s) red[tid] += red[tid + s];
        __syncthreads();
    }
    if (tid == 0) g_pd2[n] = red[0];
    __syncthreads();
    if (msk) {
        red[tid] = (tid < D2) ? sx[tid] * g_vs2[tid] : 0.f;
        __syncthreads();
        for (int s = 128; s > 0; s >>= 1) {
            if (tid < s) red[tid] += red[tid + s];
            __syncthreads();
        }
        if (tid == 0) g_ps2[n] = red[0];
    }
}

// layer-2 aggregation at mask nodes, x2 = elu(h)
__global__ void k_agg2() {
    int n = blockIdx.x;
    if (!g_mask[n]) return;
    int d = threadIdx.x;  // 256
    float ps = g_ps2[n];
    int s = g_rowptr[n], e = g_rowptr[n + 1];
    float acc = 0.f, ws = 0.f;
    for (int i = s; i < e; i++) {
        int e1 = g_csr_e1[i];
        int t = g_csr_t[i];
        float z = ps + g_pd2[e1] + g_pr2[t];
        float w = expf(lrelu_neg(z));
        ws += w;
        if (d < D2) acc += w * (g_xd2[(size_t)e1 * D2 + d] + g_rp2[(size_t)t * D2 + d]);
    }
    if (d < D2) {
        float h = (g_xs2[(size_t)n * D2 + d] * ws + acc) / (ws + 1e-12f);
        g_x2[(size_t)n * D2 + d] = (h > 0.f) ? h : expm1f(h);
    }
}

// final: out[n] = l2norm(eu[n] + mask*x2[n])
__global__ void k_out(float* __restrict__ out) {
    int n = blockIdx.x;
    int tid = threadIdx.x;  // 256
    __shared__ float red[256];
    __shared__ float s_scale;
    float v = 0.f;
    int msk = g_mask[n];
    if (tid < D2) {
        v = g_eu[(size_t)n * D2 + tid];
        if (msk) v += g_x2[(size_t)n * D2 + tid];
    }
    red[tid] = v * v;
    __syncthreads();
    for (int s = 128; s > 0; s >>= 1) {
        if (tid < s) red[tid] += red[tid + s];
        __syncthreads();
    }
    if (tid == 0) s_scale = 1.f / fmaxf(sqrtf(red[0]), 1e-12f);
    __syncthreads();
    if (tid < D2) out[(size_t)n * D2 + tid] = v * s_scale;
}

// his_temp_embs broadcast: out2[i,j,d] = he[i,d]
__global__ void k_his(float* __restrict__ out) {
    const size_t TOTAL = (size_t)BATCH * BATCH * HD;
    const size_t OFF = (size_t)NND * D2;
    size_t idx = (size_t)blockIdx.x * blockDim.x + threadIdx.x;
    size_t stride = (size_t)gridDim.x * blockDim.x;
    for (size_t i = idx; i < TOTAL; i += stride) {
        int d = (int)(i % HD);
        int b1 = (int)(i / ((size_t)BATCH * HD));
        out[OFF + i] = g_he[b1 * HD + d];
    }
}

// ---------------- launcher ----------------
extern "C" void kernel_launch(void* const* d_in, const int* in_sizes, int n_in,
                              void* d_out, int out_size) {
    const float* x     = (const float*)d_in[0];   // entity_embeddings [N,100]
    const float* rel   = (const float*)d_in[1];   // relation_table [200,100]
    const float* wt2   = (const float*)d_in[2];   // weight_t2 [1,100]
    const float* bt2   = (const float*)d_in[3];   // bias_t2 [1,100]
    const float* W_ent = (const float*)d_in[4];   // [100,200]
    const float* a_h   = (const float*)d_in[5];   // [2,100,300]
    const float* a2_h  = (const float*)d_in[6];   // [2,100]
    const float* W_rel = (const float*)d_in[7];   // [100,200]
    const float* a_o   = (const float*)d_in[8];   // [200,600]
    const float* a2_o  = (const float*)d_in[9];   // [200]
    const int* el      = (const int*)d_in[10];    // [2,E]
    const int* et      = (const int*)d_in[11];    // [E]
    const int* bi      = (const int*)d_in[12];    // [512,4]
    float* out = (float*)d_out;
    (void)in_sizes; (void)n_in; (void)out_size;

    // Resolve TRUE device addresses of __device__ globals used as kernel
    // arguments (host-side symbol references give the host shadow — the R1 bug).
    void *p_xn = nullptr, *p_xd1 = nullptr, *p_eu = nullptr;
    cudaGetSymbolAddress(&p_xn, g_xn);
    cudaGetSymbolAddress(&p_xd1, g_xd1);
    cudaGetSymbolAddress(&p_eu, g_eu);
    float* d_xn = (float*)p_xn;
    float* d_xd1 = (float*)p_xd1;
    float* d_eu = (float*)p_eu;

    // phase 0: clear + flags + small precomputes
    k_clear<<<256, 256>>>();
    k_mask<<<1, 512>>>(bi);
    k_pre_small<<<BATCH + 4, 256>>>(bi, wt2, bt2, et, a_h, a2_h, a_o, a2_o);
    k_pre_mats<<<(2 * NREL * NHID + NREL * D2 + 2 * NREL + 255) / 256, 256>>>(rel, a_h, W_rel);
    k_pre2<<<(NREL * D2 + NREL + 255) / 256, 256>>>(a_o);

    // phase 1: CSR build (by edge0)
    k_hist_flags<<<(EE + 255) / 256, 256>>>(el);
    k_scan<<<1, 1024>>>();
    k_scatter<<<(EE + 255) / 256, 256>>>(el, et);

    // phase 2: node-level projections
    k_xn<<<(NND * 32 + 127) / 128, 128>>>(x);
    k_vecs<<<(NND * 32 + 127) / 128, 128>>>(x);
    // xd1 per head (all N): C = x @ a_dst_h^T
    k_gemm<1><<<dim3((NND + 127) / 128, 1), 256>>>(
        x, a_h + 0 * NHID * 300 + 100, d_xd1, NND, FINN, NHID, FINN, 300, NHID);
    k_gemm<1><<<dim3((NND + 127) / 128, 1), 256>>>(
        x, a_h + 1 * NHID * 300 + 100, d_xd1 + (size_t)NND * NHID, NND, FINN, NHID, FINN, 300, NHID);
    // entities_upgraded = xn @ W_entities  (B is [K,O])
    k_gemm<0><<<dim3((NND + 127) / 128, 2), 256>>>(
        d_xn, W_ent, d_eu, NND, FINN, D2, FINN, D2, D2);
    // xs1 only at need1 nodes
    k_xs1<<<NND, 128>>>(x, a_h);

    // phase 3: GAT layers (pruned)
    k_agg1<<<NND, 128>>>();
    k_proj2<<<NND, 256>>>(a_o);
    k_agg2<<<NND, 256>>>();

    // phase 4: outputs
    k_out<<<NND, 256>>>(out);
    k_his<<<(BATCH * BATCH * HD + 255) / 256, 256>>>(out);
}

// round 3
// speedup vs baseline: 1.4920x; 1.4920x over previous
#include <cuda_runtime.h>
#include <math.h>

// ---------------- problem constants ----------------
#define NND   50000
#define FINN  100
#define NHID  100
#define EE    800000
#define NREL  200
#define BATCH 512
#define HD    100
#define D2    200

// ---------------- device scratch ----------------
__device__ int g_cnt[NND];
__device__ int g_cur[NND];
__device__ int g_rowptr[NND + 1];
__device__ int g_mask[NND];
__device__ int g_needflag[NND];
__device__ int g_need_idx[NND];
__device__ int g_need_list[NND];
__device__ int g_mask_list[BATCH];
__device__ int g_nneed, g_nmask;
__device__ int g_csr_e1[EE];
__device__ int g_csr_t[EE];
__device__ int g_t2map[NREL];

__device__ float g_vs1[2 * FINN], g_vd1[2 * FINN], g_vr1[2 * FINN];
__device__ float g_vs2[D2], g_vd2[D2], g_vr2[D2];
__device__ float g_rp1[2 * NREL * NHID];
__device__ float g_pr1[2 * NREL];
__device__ float g_RT2[NREL * D2];
__device__ float g_RT2g[NREL * D2];
__device__ float g_rp2[NREL * D2];
__device__ float g_pr2[NREL];
__device__ float g_he[BATCH * HD];

__device__ float g_xn[NND * FINN];      // normalized x (all N)
__device__ float g_xg[NND * FINN];      // gathered x rows (compact)
__device__ float g_ps1[2 * NND], g_pd1[2 * NND];
__device__ float g_xd1[2 * NND * NHID]; // all N, per head
__device__ float g_xs1[2 * NND * NHID]; // compact rows, per head (stride NND*NHID)
__device__ float g_x1[NND * D2];        // compact
__device__ float g_xd2[NND * D2];       // compact
__device__ float g_xs2[NND * D2];       // compact
__device__ float g_ps2[NND], g_pd2[NND];// compact
__device__ float g_x2[NND * D2];        // compact (mask rows valid)
__device__ float g_eu[NND * D2];        // all N

__device__ __forceinline__ float lrelu_neg(float z) {
    return (z >= 0.f) ? -z : -0.2f * z;
}

// ---------------- kernels ----------------

__global__ void k_clear() {
    int i = blockIdx.x * blockDim.x + threadIdx.x;
    int stride = gridDim.x * blockDim.x;
    if (i == 0) { g_nneed = 0; g_nmask = 0; }
    for (int idx = i; idx < 4 * NND; idx += stride) {
        int which = idx / NND, j = idx % NND;
        if (which == 0) g_cnt[j] = 0;
        else if (which == 1) g_cur[j] = 0;
        else if (which == 2) g_mask[j] = 0;
        else g_needflag[j] = 0;
    }
}

__global__ void k_mask(const int* __restrict__ bi) {
    int b = threadIdx.x;
    if (b < BATCH) {
        int node = bi[b * 4 + 2];
        g_mask[node] = 1;
        g_needflag[node] = 1;
    }
}

// he table, t2map, combined logit vectors (all coalesced)
__global__ void k_pre_small(const int* __restrict__ bi,
                            const float* __restrict__ wt2,
                            const float* __restrict__ bt2,
                            const int* __restrict__ etype,
                            const float* __restrict__ a_h,
                            const float* __restrict__ a2_h,
                            const float* __restrict__ a_o,
                            const float* __restrict__ a2_o) {
    int blk = blockIdx.x;
    int tid = threadIdx.x;  // 256
    if (blk < BATCH) {
        if (tid < HD) {
            float tf = (float)bi[blk * 4 + 3];
            float arg = __fadd_rn(__fmul_rn(tf, wt2[tid]), bt2[tid]);
            g_he[blk * HD + tid] = (float)cos((double)arg);
        }
    } else if (blk == BATCH) {
        if (tid < NREL) g_t2map[tid] = etype[tid];
    } else if (blk == BATCH + 1 || blk == BATCH + 2) {
        int h = blk - (BATCH + 1);
        if (tid < FINN) {
            float s0 = 0.f, s1 = 0.f, s2 = 0.f;
            for (int o = 0; o < NHID; o++) {
                float a2v = a2_h[h * NHID + o];
                const float* row = a_h + (size_t)h * NHID * 300 + (size_t)o * 300;
                s0 += row[tid] * a2v;
                s1 += row[100 + tid] * a2v;
                s2 += row[200 + tid] * a2v;
            }
            g_vs1[h * FINN + tid] = s0;
            g_vd1[h * FINN + tid] = s1;
            g_vr1[h * FINN + tid] = s2;
        }
    } else if (blk == BATCH + 3) {
        if (tid < D2) {
            float s0 = 0.f, s1 = 0.f, s2 = 0.f;
            for (int o = 0; o < D2; o++) {
                float a2v = a2_o[o];
                const float* row = a_o + (size_t)o * 600;
                s0 += row[tid] * a2v;
                s1 += row[200 + tid] * a2v;
                s2 += row[400 + tid] * a2v;
            }
            g_vs2[tid] = s0;
            g_vd2[tid] = s1;
            g_vr2[tid] = s2;
        }
    }
}

__global__ void k_hist_flags(const int* __restrict__ el) {
    int e = blockIdx.x * blockDim.x + threadIdx.x;
    if (e >= EE) return;
    int e0 = el[e];
    int e1 = el[EE + e];
    atomicAdd(&g_cnt[e0], 1);
    if (g_mask[e0]) g_needflag[e1] = 1;
}

__global__ void k_compact() {
    int n = blockIdx.x * blockDim.x + threadIdx.x;
    if (n >= NND) return;
    if (g_needflag[n]) {
        int idx = atomicAdd(&g_nneed, 1);
        g_need_list[idx] = n;
        g_need_idx[n] = idx;
    }
    if (g_mask[n]) {
        int j = atomicAdd(&g_nmask, 1);
        g_mask_list[j] = n;
    }
}

__global__ void k_scan() {
    __shared__ int sm[1024];
    int t = threadIdx.x;
    const int CH = 49;
    int base = t * CH;
    int s = 0;
    for (int i = 0; i < CH; i++) {
        int idx = base + i;
        if (idx < NND) s += g_cnt[idx];
    }
    sm[t] = s;
    __syncthreads();
    for (int off = 1; off < 1024; off <<= 1) {
        int v = 0;
        if (t >= off) v = sm[t - off];
        __syncthreads();
        if (t >= off) sm[t] += v;
        __syncthreads();
    }
    int run = (t == 0) ? 0 : sm[t - 1];
    for (int i = 0; i < CH; i++) {
        int idx = base + i;
        if (idx < NND) {
            g_rowptr[idx] = run;
            run += g_cnt[idx];
        }
    }
    if (t == 1023) g_rowptr[NND] = run;
}

__global__ void k_scatter(const int* __restrict__ el, const int* __restrict__ etype) {
    int e = blockIdx.x * blockDim.x + threadIdx.x;
    if (e >= EE) return;
    int e0 = el[e];
    int pos = g_rowptr[e0] + atomicAdd(&g_cur[e0], 1);
    g_csr_e1[pos] = el[EE + e];
    g_csr_t[pos] = etype[e];
}

// fused: xn (l2-normalized x) + per-node logit scalars ps1/pd1 (one x read)
__global__ void k_xnvecs(const float* __restrict__ x) {
    int warp = (blockIdx.x * blockDim.x + threadIdx.x) >> 5;
    int lane = threadIdx.x & 31;
    if (warp >= NND) return;
    const float* row = x + (size_t)warp * FINN;
    float ss = 0.f, a0 = 0.f, a1 = 0.f, b0 = 0.f, b1 = 0.f;
    float v0 = 0.f, v1 = 0.f, v2 = 0.f, v3 = 0.f;
    {
        int k = lane;
        v0 = row[k];
        if (k + 32 < FINN) v1 = row[k + 32];
        if (k + 64 < FINN) v2 = row[k + 64];
        if (k + 96 < FINN) v3 = row[k + 96];
    }
    ss = v0 * v0 + v1 * v1 + v2 * v2 + v3 * v3;
    {
        int k = lane;
        a0 += v0 * g_vs1[k];        a1 += v0 * g_vs1[FINN + k];
        b0 += v0 * g_vd1[k];        b1 += v0 * g_vd1[FINN + k];
        if (k + 32 < FINN) {
            a0 += v1 * g_vs1[k+32]; a1 += v1 * g_vs1[FINN+k+32];
            b0 += v1 * g_vd1[k+32]; b1 += v1 * g_vd1[FINN+k+32];
        }
        if (k + 64 < FINN) {
            a0 += v2 * g_vs1[k+64]; a1 += v2 * g_vs1[FINN+k+64];
            b0 += v2 * g_vd1[k+64]; b1 += v2 * g_vd1[FINN+k+64];
        }
        if (k + 96 < FINN) {
            a0 += v3 * g_vs1[k+96]; a1 += v3 * g_vs1[FINN+k+96];
            b0 += v3 * g_vd1[k+96]; b1 += v3 * g_vd1[FINN+k+96];
        }
    }
    for (int o = 16; o > 0; o >>= 1) {
        ss += __shfl_xor_sync(0xffffffffu, ss, o);
        a0 += __shfl_xor_sync(0xffffffffu, a0, o);
        a1 += __shfl_xor_sync(0xffffffffu, a1, o);
        b0 += __shfl_xor_sync(0xffffffffu, b0, o);
        b1 += __shfl_xor_sync(0xffffffffu, b1, o);
    }
    ss = __shfl_sync(0xffffffffu, ss, 0);
    float scale = 1.f / fmaxf(sqrtf(ss), 1e-12f);
    float* dst = g_xn + (size_t)warp * FINN;
    {
        int k = lane;
        dst[k] = v0 * scale;
        if (k + 32 < FINN) dst[k + 32] = v1 * scale;
        if (k + 64 < FINN) dst[k + 64] = v2 * scale;
        if (k + 96 < FINN) dst[k + 96] = v3 * scale;
    }
    if (lane == 0) {
        g_ps1[warp] = a0;
        g_ps1[NND + warp] = a1;
        g_pd1[warp] = b0;
        g_pd1[NND + warp] = b1;
    }
}

// gather x rows of need-list into dense g_xg (float4)
__global__ void k_gather_xg(const float* __restrict__ x) {
    int nneed = g_nneed;
    int total = nneed * (FINN / 4);
    int idx = blockIdx.x * blockDim.x + threadIdx.x;
    int stride = gridDim.x * blockDim.x;
    const float4* xs = (const float4*)x;
    float4* xd = (float4*)g_xg;
    for (int j = idx; j < total; j += stride) {
        int i = j / (FINN / 4), c = j % (FINN / 4);
        int n = g_need_list[i];
        xd[(size_t)i * (FINN / 4) + c] = xs[(size_t)n * (FINN / 4) + c];
    }
}

// gather RT2 rows composed with t2map
__global__ void k_gatherRT2() {
    int idx = blockIdx.x * blockDim.x + threadIdx.x;
    if (idx >= NREL * D2) return;
    int t = idx / D2, k = idx % D2;
    g_RT2g[idx] = g_RT2[(size_t)g_t2map[t] * D2 + k];
}

// pr1[h,t] = rel[t]·vr1[h]   (warp per (h,t))
__global__ void k_pr1(const float* __restrict__ rel) {
    int w = (blockIdx.x * blockDim.x + threadIdx.x) >> 5;
    int lane = threadIdx.x & 31;
    if (w >= 2 * NREL) return;
    int h = w / NREL, t = w % NREL;
    const float* rrow = rel + (size_t)t * 100;
    float s = 0.f;
    for (int k = lane; k < 100; k += 32) s += rrow[k] * g_vr1[h * FINN + k];
    for (int o = 16; o > 0; o >>= 1) s += __shfl_xor_sync(0xffffffffu, s, o);
    if (lane == 0) g_pr1[h * NREL + t] = s;
}

// pr2[t] = RT2g[t]·vr2   (warp per t)
__global__ void k_pr2() {
    int w = (blockIdx.x * blockDim.x + threadIdx.x) >> 5;
    int lane = threadIdx.x & 31;
    if (w >= NREL) return;
    const float* rrow = g_RT2g + (size_t)w * D2;
    float s = 0.f;
    for (int k = lane; k < D2; k += 32) s += rrow[k] * g_vr2[k];
    for (int o = 16; o > 0; o >>= 1) s += __shfl_xor_sync(0xffffffffu, s, o);
    if (lane == 0) g_pr2[w] = s;
}

// Tiled SGEMM: C[M,O] = A[M,K] * op(B). TRANSB=1: B[O,K] rows stride ldb.
// M from *Mptr if non-null (dynamic compact count).
template <int TRANSB>
__global__ void k_gemm(const float* __restrict__ A, const float* __restrict__ B,
                       float* __restrict__ C, const int* __restrict__ Mptr,
                       int Mconst, int K, int O, int lda, int ldb, int ldc) {
    const int BM = 128, BN = 128, BK = 20;
    __shared__ float As[BK][BM + 4];
    __shared__ float Bs[BK][BN + 4];
    int M = Mptr ? *Mptr : Mconst;
    int m0 = blockIdx.x * BM, o0 = blockIdx.y * BN;
    if (m0 >= M) return;
    int tid = threadIdx.x;  // 256
    int tx = tid % 16, ty = tid / 16;
    float acc[8][8];
#pragma unroll
    for (int i = 0; i < 8; i++)
#pragma unroll
        for (int j = 0; j < 8; j++) acc[i][j] = 0.f;

    for (int k0 = 0; k0 < K; k0 += BK) {
        for (int i = tid; i < BM * BK; i += 256) {
            int m = i / BK, k = i % BK;
            int gm = m0 + m, gk = k0 + k;
            As[k][m] = (gm < M && gk < K) ? A[(size_t)gm * lda + gk] : 0.f;
        }
        for (int i = tid; i < BN * BK; i += 256) {
            int o, k;
            float v = 0.f;
            if (TRANSB) {
                o = i / BK; k = i % BK;
                int go = o0 + o, gk = k0 + k;
                if (go < O && gk < K) v = B[(size_t)go * ldb + gk];
            } else {
                o = i % BN; k = i / BN;
                int go = o0 + o, gk = k0 + k;
                if (go < O && gk < K) v = B[(size_t)gk * ldb + go];
            }
            Bs[k][o] = v;
        }
        __syncthreads();
#pragma unroll
        for (int kk = 0; kk < BK; kk++) {
            float a[8], b[8];
#pragma unroll
            for (int i = 0; i < 8; i++) { a[i] = As[kk][ty * 8 + i]; b[i] = Bs[kk][tx * 8 + i]; }
#pragma unroll
            for (int i = 0; i < 8; i++)
#pragma unroll
                for (int j = 0; j < 8; j++) acc[i][j] += a[i] * b[j];
        }
        __syncthreads();
    }
#pragma unroll
    for (int i = 0; i < 8; i++) {
        int gm = m0 + ty * 8 + i;
        if (gm >= M) continue;
#pragma unroll
        for (int j = 0; j < 8; j++) {
            int go = o0 + tx * 8 + j;
            if (go < O) C[(size_t)gm * ldc + go] = acc[i][j];
        }
    }
}

// layer-1 aggregation over compact list (block-stride)
__global__ void k_agg1() {
    int d = threadIdx.x;  // 128
    int nneed = g_nneed;
    for (int i = blockIdx.x; i < nneed; i += gridDim.x) {
        int n = g_need_list[i];
        float ps_a = g_ps1[n];
        float ps_b = g_ps1[NND + n];
        int s = g_rowptr[n], e = g_rowptr[n + 1];
        float acc0 = 0.f, acc1 = 0.f, ws0 = 0.f, ws1 = 0.f;
        for (int j = s; j < e; j++) {
            int e1 = g_csr_e1[j];
            int t = g_csr_t[j];
            float z0 = ps_a + g_pd1[e1] + g_pr1[t];
            float z1 = ps_b + g_pd1[NND + e1] + g_pr1[NREL + t];
            float w0 = expf(lrelu_neg(z0));
            float w1 = expf(lrelu_neg(z1));
            ws0 += w0;
            ws1 += w1;
            if (d < NHID) {
                acc0 += w0 * (g_xd1[(size_t)e1 * NHID + d] + g_rp1[(size_t)t * NHID + d]);
                acc1 += w1 * (g_xd1[((size_t)NND + e1) * NHID + d] +
                              g_rp1[((size_t)NREL + t) * NHID + d]);
            }
        }
        if (d < NHID) {
            float h0 = (g_xs1[(size_t)i * NHID + d] * ws0 + acc0) / (ws0 + 1e-12f);
            float h1 = (g_xs1[((size_t)NND + i) * NHID + d] * ws1 + acc1) / (ws1 + 1e-12f);
            g_x1[(size_t)i * D2 + d] = (h0 > 0.f) ? h0 : expm1f(h0);
            g_x1[(size_t)i * D2 + NHID + d] = (h1 > 0.f) ? h1 : expm1f(h1);
        }
    }
}

// pd2/ps2 over compact rows (warp per row)
__global__ void k_pdps() {
    int w = (blockIdx.x * blockDim.x + threadIdx.x) >> 5;
    int lane = threadIdx.x & 31;
    int nwarp = (gridDim.x * blockDim.x) >> 5;
    int nneed = g_nneed;
    for (int i = w; i < nneed; i += nwarp) {
        const float* row = g_x1 + (size_t)i * D2;
        float a = 0.f, b = 0.f;
        for (int k = lane; k < D2; k += 32) {
            float v = row[k];
            a += v * g_vd2[k];
            b += v * g_vs2[k];
        }
        for (int o = 16; o > 0; o >>= 1) {
            a += __shfl_xor_sync(0xffffffffu, a, o);
            b += __shfl_xor_sync(0xffffffffu, b, o);
        }
        if (lane == 0) { g_pd2[i] = a; g_ps2[i] = b; }
    }
}

// layer-2 aggregation at mask nodes (block-stride over mask list)
__global__ void k_agg2() {
    int d = threadIdx.x;  // 256
    int nmask = g_nmask;
    for (int m = blockIdx.x; m < nmask; m += gridDim.x) {
        int n = g_mask_list[m];
        int ii = g_need_idx[n];
        float ps = g_ps2[ii];
        int s = g_rowptr[n], e = g_rowptr[n + 1];
        float acc = 0.f, ws = 0.f;
        for (int j = s; j < e; j++) {
            int e1 = g_csr_e1[j];
            int t = g_csr_t[j];
            int i1 = g_need_idx[e1];
            float z = ps + g_pd2[i1] + g_pr2[t];
            float w = expf(lrelu_neg(z));
            ws += w;
            if (d < D2) acc += w * (g_xd2[(size_t)i1 * D2 + d] + g_rp2[(size_t)t * D2 + d]);
        }
        if (d < D2) {
            float h = (g_xs2[(size_t)ii * D2 + d] * ws + acc) / (ws + 1e-12f);
            g_x2[(size_t)ii * D2 + d] = (h > 0.f) ? h : expm1f(h);
        }
    }
}

// out[n] = l2norm(eu[n] + mask*x2[n])
__global__ void k_out(float* __restrict__ out) {
    int n = blockIdx.x;
    int tid = threadIdx.x;  // 256
    __shared__ float red[256];
    __shared__ float s_scale;
    float v = 0.f;
    int msk = g_mask[n];
    if (tid < D2) {
        v = g_eu[(size_t)n * D2 + tid];
        if (msk) v += g_x2[(size_t)g_need_idx[n] * D2 + tid];
    }
    red[tid] = v * v;
    __syncthreads();
    for (int s = 128; s > 0; s >>= 1) {
        if (tid < s) red[tid] += red[tid + s];
        __syncthreads();
    }
    if (tid == 0) s_scale = 1.f / fmaxf(sqrtf(red[0]), 1e-12f);
    __syncthreads();
    if (tid < D2) out[(size_t)n * D2 + tid] = v * s_scale;
}

// his broadcast, float4 (HD=100 divisible by 4)
__global__ void k_his(float* __restrict__ out) {
    const size_t TOT4 = (size_t)BATCH * BATCH * (HD / 4);
    const size_t OFF4 = ((size_t)NND * D2) / 4;
    const float4* he4 = (const float4*)g_he;
    float4* o4 = (float4*)out;
    size_t idx = (size_t)blockIdx.x * blockDim.x + threadIdx.x;
    size_t stride = (size_t)gridDim.x * blockDim.x;
    for (size_t j = idx; j < TOT4; j += stride) {
        int c = (int)(j % (HD / 4));
        int b1 = (int)(j / ((size_t)BATCH * (HD / 4)));
        o4[OFF4 + j] = he4[b1 * (HD / 4) + c];
    }
}

// ---------------- launcher ----------------
extern "C" void kernel_launch(void* const* d_in, const int* in_sizes, int n_in,
                              void* d_out, int out_size) {
    const float* x     = (const float*)d_in[0];
    const float* rel   = (const float*)d_in[1];
    const float* wt2   = (const float*)d_in[2];
    const float* bt2   = (const float*)d_in[3];
    const float* W_ent = (const float*)d_in[4];
    const float* a_h   = (const float*)d_in[5];
    const float* a2_h  = (const float*)d_in[6];
    const float* W_rel = (const float*)d_in[7];
    const float* a_o   = (const float*)d_in[8];
    const float* a2_o  = (const float*)d_in[9];
    const int* el      = (const int*)d_in[10];
    const int* et      = (const int*)d_in[11];
    const int* bi      = (const int*)d_in[12];
    float* out = (float*)d_out;
    (void)in_sizes; (void)n_in; (void)out_size;

    // resolve TRUE device addresses for symbols passed as kernel arguments
    void *p;
    cudaGetSymbolAddress(&p, g_xn);    float* d_xn   = (float*)p;
    cudaGetSymbolAddress(&p, g_xg);    float* d_xg   = (float*)p;
    cudaGetSymbolAddress(&p, g_xd1);   float* d_xd1  = (float*)p;
    cudaGetSymbolAddress(&p, g_xs1);   float* d_xs1  = (float*)p;
    cudaGetSymbolAddress(&p, g_eu);    float* d_eu   = (float*)p;
    cudaGetSymbolAddress(&p, g_x1);    float* d_x1   = (float*)p;
    cudaGetSymbolAddress(&p, g_xd2);   float* d_xd2  = (float*)p;
    cudaGetSymbolAddress(&p, g_xs2);   float* d_xs2  = (float*)p;
    cudaGetSymbolAddress(&p, g_rp1);   float* d_rp1  = (float*)p;
    cudaGetSymbolAddress(&p, g_RT2);   float* d_RT2  = (float*)p;
    cudaGetSymbolAddress(&p, g_RT2g);  float* d_RT2g = (float*)p;
    cudaGetSymbolAddress(&p, g_rp2);   float* d_rp2  = (float*)p;
    cudaGetSymbolAddress(&p, g_nneed); const int* d_nneed = (const int*)p;

    const int GA = (NND + 127) / 128;   // 391 row-blocks for M<=NND

    // phase 0: clear + flags + small precomputes
    k_clear<<<256, 256>>>();
    k_mask<<<1, 512>>>(bi);
    k_pre_small<<<BATCH + 4, 256>>>(bi, wt2, bt2, et, a_h, a2_h, a_o, a2_o);

    // phase 1: CSR + compaction
    k_hist_flags<<<(EE + 255) / 256, 256>>>(el);
    k_compact<<<(NND + 255) / 256, 256>>>();
    k_scan<<<1, 1024>>>();
    k_scatter<<<(EE + 255) / 256, 256>>>(el, et);

    // phase 2: relation-side precomputes via tiled GEMM (coalesced)
    // rp1[h] = rel @ a_rel_h^T
    k_gemm<1><<<dim3(2, 1), 256>>>(rel, a_h + 200, d_rp1, nullptr,
                                   NREL, 100, NHID, 100, 300, NHID);
    k_gemm<1><<<dim3(2, 1), 256>>>(rel, a_h + (size_t)NHID * 300 + 200,
                                   d_rp1 + NREL * NHID, nullptr,
                                   NREL, 100, NHID, 100, 300, NHID);
    // RT2 = rel @ W_rel
    k_gemm<0><<<dim3(2, 2), 256>>>(rel, W_rel, d_RT2, nullptr,
                                   NREL, 100, D2, 100, D2, D2);
    k_pr1<<<(2 * NREL * 32 + 255) / 256, 256>>>(rel);
    k_gatherRT2<<<(NREL * D2 + 255) / 256, 256>>>();
    // rp2 = RT2g @ a_rel2^T
    k_gemm<1><<<dim3(2, 2), 256>>>(d_RT2g, a_o + 400, d_rp2, nullptr,
                                   NREL, D2, D2, D2, 600, D2);
    k_pr2<<<(NREL * 32 + 255) / 256, 256>>>();

    // phase 3: node-level projections
    k_xnvecs<<<(NND * 32 + 127) / 128, 128>>>(x);
    k_gemm<1><<<dim3(GA, 1), 256>>>(x, a_h + 100, d_xd1, nullptr,
                                    NND, FINN, NHID, FINN, 300, NHID);
    k_gemm<1><<<dim3(GA, 1), 256>>>(x, a_h + (size_t)NHID * 300 + 100,
                                    d_xd1 + (size_t)NND * NHID, nullptr,
                                    NND, FINN, NHID, FINN, 300, NHID);
    k_gemm<0><<<dim3(GA, 2), 256>>>(d_xn, W_ent, d_eu, nullptr,
                                    NND, FINN, D2, FINN, D2, D2);
    // gather compact x rows, then xs1 per head (dynamic M)
    k_gather_xg<<<512, 256>>>(x);
    k_gemm<1><<<dim3(GA, 1), 256>>>(d_xg, a_h, d_xs1, d_nneed,
                                    0, FINN, NHID, FINN, 300, NHID);
    k_gemm<1><<<dim3(GA, 1), 256>>>(d_xg, a_h + (size_t)NHID * 300,
                                    d_xs1 + (size_t)NND * NHID, d_nneed,
                                    0, FINN, NHID, FINN, 300, NHID);

    // phase 4: GAT layers (compact)
    k_agg1<<<2048, 128>>>();
    // xd2 = x1c @ a_dst2^T ; xs2 = x1c @ a_src2^T  (dynamic M)
    k_gemm<1><<<dim3(GA, 2), 256>>>(d_x1, a_o + 200, d_xd2, d_nneed,
                                    0, D2, D2, D2, 600, D2);
    k_gemm<1><<<dim3(GA, 2), 256>>>(d_x1, a_o, d_xs2, d_nneed,
                                    0, D2, D2, D2, 600, D2);
    k_pdps<<<512, 256>>>();
    k_agg2<<<512, 256>>>();

    // phase 5: outputs
    k_out<<<NND, 256>>>(out);
    k_his<<<2048, 256>>>(out);
}

// round 4
// speedup vs baseline: 1.9261x; 1.2909x over previous
#include <cuda_runtime.h>
#include <math.h>

// ---------------- problem constants ----------------
#define NND   50000
#define FINN  100
#define NHID  100
#define EE    800000
#define NREL  200
#define BATCH 512
#define HD    100
#define D2    200

// ---------------- device scratch ----------------
__device__ int g_cnt[NND];
__device__ int g_cur[NND];
__device__ int g_rowptr[NND + 1];
__device__ int g_mask[NND];
__device__ int g_needflag[NND];
__device__ int g_need_idx[NND];
__device__ int g_need_list[NND];
__device__ int g_mask_list[BATCH];
__device__ int g_nneed, g_nmask;
__device__ int g_csr_e1[EE];
__device__ int g_csr_t[EE];
__device__ int g_t2map[NREL];

__device__ float g_vs1[2 * FINN], g_vd1[2 * FINN], g_vr1[2 * FINN];
__device__ float g_vs2[D2], g_vd2[D2], g_vr2[D2];
__device__ float g_he[BATCH * HD];
__device__ float g_pr1[2 * NREL];
__device__ float g_pr2[NREL];

// packed B matrices (all [O, K] row-major)
__device__ float g_Bp1[400 * 100];   // rel-side: [a_rel h0; a_rel h1; W_rel^T]
__device__ float g_Bp2[400 * 100];   // node-side: [a_dst h0; a_dst h1; W_ent^T]
__device__ float g_Bp3[200 * 100];   // xs1: [a_src h0; a_src h1]
__device__ float g_Bp4[400 * 200];   // layer2: [a_dst2; a_src2]

__device__ float g_relC[NREL * 400]; // cols 0-99 rp1 h0, 100-199 rp1 h1, 200-399 RT2
__device__ float g_RT2g[NREL * D2];  // RT2 composed with t2map
__device__ float g_rp2[NREL * D2];

__device__ float g_invn[NND];
__device__ float g_ps1[2 * NND], g_pd1[2 * NND];
__device__ float g_big[(size_t)NND * 400];  // cols 0-199: xd1(h0,h1); 200-399: eu
__device__ float g_xg[NND * FINN];          // gathered x (compact)
__device__ float g_xs1[NND * D2];           // compact: [i, h*100+o]
__device__ float g_x1[NND * D2];            // compact
__device__ float g_l2[(size_t)NND * 400];   // compact: 0-199 xd2, 200-399 xs2
__device__ float g_ps2[NND], g_pd2[NND];    // compact
__device__ float g_x2[NND * D2];            // compact

__device__ __forceinline__ float lrelu_neg(float z) {
    return (z >= 0.f) ? -z : -0.2f * z;
}

// ---------------- kernels ----------------

__global__ void k_clear() {
    int i = blockIdx.x * blockDim.x + threadIdx.x;
    int stride = gridDim.x * blockDim.x;
    if (i == 0) { g_nneed = 0; g_nmask = 0; }
    for (int idx = i; idx < 4 * NND; idx += stride) {
        int which = idx / NND, j = idx % NND;
        if (which == 0) g_cnt[j] = 0;
        else if (which == 1) g_cur[j] = 0;
        else if (which == 2) g_mask[j] = 0;
        else g_needflag[j] = 0;
    }
}

__global__ void k_mask(const int* __restrict__ bi) {
    int b = threadIdx.x;
    if (b < BATCH) {
        int node = bi[b * 4 + 2];
        g_mask[node] = 1;
        g_needflag[node] = 1;
    }
}

// he table, t2map, combined logit vectors
__global__ void k_pre_small(const int* __restrict__ bi,
                            const float* __restrict__ wt2,
                            const float* __restrict__ bt2,
                            const int* __restrict__ etype,
                            const float* __restrict__ a_h,
                            const float* __restrict__ a2_h,
                            const float* __restrict__ a_o,
                            const float* __restrict__ a2_o) {
    int blk = blockIdx.x;
    int tid = threadIdx.x;  // 256
    if (blk < BATCH) {
        if (tid < HD) {
            float tf = (float)bi[blk * 4 + 3];
            float arg = __fadd_rn(__fmul_rn(tf, wt2[tid]), bt2[tid]);
            g_he[blk * HD + tid] = (float)cos((double)arg);
        }
    } else if (blk == BATCH) {
        if (tid < NREL) g_t2map[tid] = etype[tid];
    } else if (blk == BATCH + 1 || blk == BATCH + 2) {
        int h = blk - (BATCH + 1);
        if (tid < FINN) {
            float s0 = 0.f, s1 = 0.f, s2 = 0.f;
            for (int o = 0; o < NHID; o++) {
                float a2v = a2_h[h * NHID + o];
                const float* row = a_h + (size_t)h * NHID * 300 + (size_t)o * 300;
                s0 += row[tid] * a2v;
                s1 += row[100 + tid] * a2v;
                s2 += row[200 + tid] * a2v;
            }
            g_vs1[h * FINN + tid] = s0;
            g_vd1[h * FINN + tid] = s1;
            g_vr1[h * FINN + tid] = s2;
        }
    } else if (blk == BATCH + 3) {
        if (tid < D2) {
            float s0 = 0.f, s1 = 0.f, s2 = 0.f;
            for (int o = 0; o < D2; o++) {
                float a2v = a2_o[o];
                const float* row = a_o + (size_t)o * 600;
                s0 += row[tid] * a2v;
                s1 += row[200 + tid] * a2v;
                s2 += row[400 + tid] * a2v;
            }
            g_vs2[tid] = s0;
            g_vd2[tid] = s1;
            g_vr2[tid] = s2;
        }
    }
}

// build all packed B matrices (coalesced-ish copies; total 180k elems)
__global__ void k_pack(const float* __restrict__ a_h,
                       const float* __restrict__ W_rel,
                       const float* __restrict__ W_ent,
                       const float* __restrict__ a_o) {
    int idx = blockIdx.x * blockDim.x + threadIdx.x;
    int stride = gridDim.x * blockDim.x;
    const int T1 = 400 * 100, T2 = 400 * 100, T3 = 200 * 100, T4 = 400 * 200;
    for (int i = idx; i < T1 + T2 + T3 + T4; i += stride) {
        if (i < T1) {
            int r = i / 100, k = i % 100;
            float v;
            if (r < 200) {
                int h = r / 100, o = r % 100;
                v = a_h[(size_t)h * 100 * 300 + (size_t)o * 300 + 200 + k];
            } else {
                v = W_rel[(size_t)k * 200 + (r - 200)];
            }
            g_Bp1[i] = v;
        } else if (i < T1 + T2) {
            int j = i - T1;
            int r = j / 100, k = j % 100;
            float v;
            if (r < 200) {
                int h = r / 100, o = r % 100;
                v = a_h[(size_t)h * 100 * 300 + (size_t)o * 300 + 100 + k];
            } else {
                v = W_ent[(size_t)k * 200 + (r - 200)];
            }
            g_Bp2[j] = v;
        } else if (i < T1 + T2 + T3) {
            int j = i - T1 - T2;
            int r = j / 100, k = j % 100;
            int h = r / 100, o = r % 100;
            g_Bp3[j] = a_h[(size_t)h * 100 * 300 + (size_t)o * 300 + k];
        } else {
            int j = i - T1 - T2 - T3;
            int r = j / 200, k = j % 200;
            float v;
            if (r < 200) v = a_o[(size_t)r * 600 + 200 + k];
            else         v = a_o[(size_t)(r - 200) * 600 + k];
            g_Bp4[j] = v;
        }
    }
}

// fused: invn + per-node logit scalars ps1/pd1 (one x read)
__global__ void k_xnvecs(const float* __restrict__ x) {
    int warp = (blockIdx.x * blockDim.x + threadIdx.x) >> 5;
    int lane = threadIdx.x & 31;
    if (warp >= NND) return;
    const float* row = x + (size_t)warp * FINN;
    float ss, a0 = 0.f, a1 = 0.f, b0 = 0.f, b1 = 0.f;
    float v0 = 0.f, v1 = 0.f, v2 = 0.f, v3 = 0.f;
    int k = lane;
    v0 = row[k];
    if (k + 32 < FINN) v1 = row[k + 32];
    if (k + 64 < FINN) v2 = row[k + 64];
    if (k + 96 < FINN) v3 = row[k + 96];
    ss = v0 * v0 + v1 * v1 + v2 * v2 + v3 * v3;
    a0 += v0 * g_vs1[k];        a1 += v0 * g_vs1[FINN + k];
    b0 += v0 * g_vd1[k];        b1 += v0 * g_vd1[FINN + k];
    if (k + 32 < FINN) {
        a0 += v1 * g_vs1[k+32]; a1 += v1 * g_vs1[FINN+k+32];
        b0 += v1 * g_vd1[k+32]; b1 += v1 * g_vd1[FINN+k+32];
    }
    if (k + 64 < FINN) {
        a0 += v2 * g_vs1[k+64]; a1 += v2 * g_vs1[FINN+k+64];
        b0 += v2 * g_vd1[k+64]; b1 += v2 * g_vd1[FINN+k+64];
    }
    if (k + 96 < FINN) {
        a0 += v3 * g_vs1[k+96]; a1 += v3 * g_vs1[FINN+k+96];
        b0 += v3 * g_vd1[k+96]; b1 += v3 * g_vd1[FINN+k+96];
    }
    for (int o = 16; o > 0; o >>= 1) {
        ss += __shfl_xor_sync(0xffffffffu, ss, o);
        a0 += __shfl_xor_sync(0xffffffffu, a0, o);
        a1 += __shfl_xor_sync(0xffffffffu, a1, o);
        b0 += __shfl_xor_sync(0xffffffffu, b0, o);
        b1 += __shfl_xor_sync(0xffffffffu, b1, o);
    }
    if (lane == 0) {
        g_invn[warp] = 1.f / fmaxf(sqrtf(ss), 1e-12f);
        g_ps1[warp] = a0;
        g_ps1[NND + warp] = a1;
        g_pd1[warp] = b0;
        g_pd1[NND + warp] = b1;
    }
}

// Tiled SGEMM: C[M,O] = A[M,K] @ B[O,K]^T.
// BM=160, BN=80, BK=20; 256 threads, 10x5 microtile.
// EPI==1: scale cols >= 200 by invn[row].
template <int EPI>
__global__ void __launch_bounds__(256, 2)
k_gemm(const float* __restrict__ A, int lda,
       const float* __restrict__ B, int ldb,
       float* __restrict__ C, int ldc,
       const int* __restrict__ Mptr, int Mconst,
       int K, int O, const float* __restrict__ invn) {
    const int BM = 160, BN = 80, BK = 20;
    __shared__ float As[BK][BM + 4];
    __shared__ float Bs[BK][BN + 4];
    int M = Mptr ? *Mptr : Mconst;
    int m0 = blockIdx.x * BM, o0 = blockIdx.y * BN;
    if (m0 >= M) return;
    int tid = threadIdx.x;
    int rx = tid % 16, ry = tid / 16;
    float acc[10][5];
#pragma unroll
    for (int i = 0; i < 10; i++)
#pragma unroll
        for (int j = 0; j < 5; j++) acc[i][j] = 0.f;

    for (int k0 = 0; k0 < K; k0 += BK) {
        for (int i = tid; i < BM * BK; i += 256) {
            int m = i / BK, k = i % BK;
            int gm = m0 + m;
            As[k][m] = (gm < M) ? A[(size_t)gm * lda + k0 + k] : 0.f;
        }
        for (int i = tid; i < BN * BK; i += 256) {
            int o = i / BK, k = i % BK;
            int go = o0 + o;
            Bs[k][o] = (go < O) ? B[(size_t)go * ldb + k0 + k] : 0.f;
        }
        __syncthreads();
#pragma unroll
        for (int kk = 0; kk < BK; kk++) {
            float a[10], b[5];
#pragma unroll
            for (int i = 0; i < 10; i++) a[i] = As[kk][ry * 10 + i];
#pragma unroll
            for (int j = 0; j < 5; j++) b[j] = Bs[kk][rx * 5 + j];
#pragma unroll
            for (int i = 0; i < 10; i++)
#pragma unroll
                for (int j = 0; j < 5; j++) acc[i][j] += a[i] * b[j];
        }
        __syncthreads();
    }
#pragma unroll
    for (int i = 0; i < 10; i++) {
        int gm = m0 + ry * 10 + i;
        if (gm >= M) continue;
        float sc = (EPI == 1) ? invn[gm] : 1.f;
#pragma unroll
        for (int j = 0; j < 5; j++) {
            int go = o0 + rx * 5 + j;
            if (go < O) {
                float v = acc[i][j];
                if (EPI == 1 && go >= 200) v *= sc;
                C[(size_t)gm * ldc + go] = v;
            }
        }
    }
}

__global__ void k_hist_flags(const int* __restrict__ el) {
    int e = blockIdx.x * blockDim.x + threadIdx.x;
    if (e >= EE) return;
    int e0 = el[e];
    int e1 = el[EE + e];
    atomicAdd(&g_cnt[e0], 1);
    if (g_mask[e0]) g_needflag[e1] = 1;
}

__global__ void k_compact() {
    int n = blockIdx.x * blockDim.x + threadIdx.x;
    if (n >= NND) return;
    if (g_needflag[n]) {
        int idx = atomicAdd(&g_nneed, 1);
        g_need_list[idx] = n;
        g_need_idx[n] = idx;
    }
    if (g_mask[n]) {
        int j = atomicAdd(&g_nmask, 1);
        g_mask_list[j] = n;
    }
}

__global__ void k_scan() {
    __shared__ int sm[1024];
    int t = threadIdx.x;
    const int CH = 49;
    int base = t * CH;
    int s = 0;
    for (int i = 0; i < CH; i++) {
        int idx = base + i;
        if (idx < NND) s += g_cnt[idx];
    }
    sm[t] = s;
    __syncthreads();
    for (int off = 1; off < 1024; off <<= 1) {
        int v = 0;
        if (t >= off) v = sm[t - off];
        __syncthreads();
        if (t >= off) sm[t] += v;
        __syncthreads();
    }
    int run = (t == 0) ? 0 : sm[t - 1];
    for (int i = 0; i < CH; i++) {
        int idx = base + i;
        if (idx < NND) {
            g_rowptr[idx] = run;
            run += g_cnt[idx];
        }
    }
    if (t == 1023) g_rowptr[NND] = run;
}

__global__ void k_scatter(const int* __restrict__ el, const int* __restrict__ etype) {
    int e = blockIdx.x * blockDim.x + threadIdx.x;
    if (e >= EE) return;
    int e0 = el[e];
    int pos = g_rowptr[e0] + atomicAdd(&g_cur[e0], 1);
    g_csr_e1[pos] = el[EE + e];
    g_csr_t[pos] = etype[e];
}

// fused: pr1 (blocks 0-49, warp per (h,t)) + RT2g gather (blocks 50+)
__global__ void k_misc1(const float* __restrict__ rel) {
    int blk = blockIdx.x;
    int tid = threadIdx.x;  // 256
    if (blk < 50) {
        int w = blk * 8 + (tid >> 5);
        int lane = tid & 31;
        if (w >= 2 * NREL) return;
        int h = w / NREL, t = w % NREL;
        const float* rrow = rel + (size_t)t * 100;
        float s = 0.f;
        for (int kk = lane; kk < 100; kk += 32) s += rrow[kk] * g_vr1[h * FINN + kk];
        for (int o = 16; o > 0; o >>= 1) s += __shfl_xor_sync(0xffffffffu, s, o);
        if (lane == 0) g_pr1[h * NREL + t] = s;
    } else {
        int idx = (blk - 50) * 256 + tid;
        if (idx < NREL * D2) {
            int t = idx / D2, kk = idx % D2;
            g_RT2g[idx] = g_relC[(size_t)g_t2map[t] * 400 + 200 + kk];
        }
    }
}

// pr2[t] = RT2g[t]·vr2
__global__ void k_pr2() {
    int w = (blockIdx.x * blockDim.x + threadIdx.x) >> 5;
    int lane = threadIdx.x & 31;
    if (w >= NREL) return;
    const float* rrow = g_RT2g + (size_t)w * D2;
    float s = 0.f;
    for (int kk = lane; kk < D2; kk += 32) s += rrow[kk] * g_vr2[kk];
    for (int o = 16; o > 0; o >>= 1) s += __shfl_xor_sync(0xffffffffu, s, o);
    if (lane == 0) g_pr2[w] = s;
}

// gather x rows of need-list into dense g_xg (float4)
__global__ void k_gather_xg(const float* __restrict__ x) {
    int nneed = g_nneed;
    int total = nneed * (FINN / 4);
    int idx = blockIdx.x * blockDim.x + threadIdx.x;
    int stride = gridDim.x * blockDim.x;
    const float4* xs = (const float4*)x;
    float4* xd = (float4*)g_xg;
    for (int j = idx; j < total; j += stride) {
        int i = j / (FINN / 4), c = j % (FINN / 4);
        int n = g_need_list[i];
        xd[(size_t)i * (FINN / 4) + c] = xs[(size_t)n * (FINN / 4) + c];
    }
}

// layer-1 aggregation over compact list
__global__ void k_agg1() {
    int d = threadIdx.x;  // 128
    int nneed = g_nneed;
    for (int i = blockIdx.x; i < nneed; i += gridDim.x) {
        int n = g_need_list[i];
        float ps_a = g_ps1[n];
        float ps_b = g_ps1[NND + n];
        int s = g_rowptr[n], e = g_rowptr[n + 1];
        float acc0 = 0.f, acc1 = 0.f, ws0 = 0.f, ws1 = 0.f;
        for (int j = s; j < e; j++) {
            int e1 = g_csr_e1[j];
            int t = g_csr_t[j];
            float z0 = ps_a + g_pd1[e1] + g_pr1[t];
            float z1 = ps_b + g_pd1[NND + e1] + g_pr1[NREL + t];
            float w0 = expf(lrelu_neg(z0));
            float w1 = expf(lrelu_neg(z1));
            ws0 += w0;
            ws1 += w1;
            if (d < NHID) {
                const float* bigrow = g_big + (size_t)e1 * 400;
                const float* rprow = g_relC + (size_t)t * 400;
                acc0 += w0 * (bigrow[d] + rprow[d]);
                acc1 += w1 * (bigrow[100 + d] + rprow[100 + d]);
            }
        }
        if (d < NHID) {
            float h0 = (g_xs1[(size_t)i * D2 + d] * ws0 + acc0) / (ws0 + 1e-12f);
            float h1 = (g_xs1[(size_t)i * D2 + 100 + d] * ws1 + acc1) / (ws1 + 1e-12f);
            g_x1[(size_t)i * D2 + d] = (h0 > 0.f) ? h0 : expm1f(h0);
            g_x1[(size_t)i * D2 + 100 + d] = (h1 > 0.f) ? h1 : expm1f(h1);
        }
    }
}

// pd2/ps2 over compact rows (warp per row)
__global__ void k_pdps() {
    int w = (blockIdx.x * blockDim.x + threadIdx.x) >> 5;
    int lane = threadIdx.x & 31;
    int nwarp = (gridDim.x * blockDim.x) >> 5;
    int nneed = g_nneed;
    for (int i = w; i < nneed; i += nwarp) {
        const float* row = g_x1 + (size_t)i * D2;
        float a = 0.f, b = 0.f;
        for (int kk = lane; kk < D2; kk += 32) {
            float v = row[kk];
            a += v * g_vd2[kk];
            b += v * g_vs2[kk];
        }
        for (int o = 16; o > 0; o >>= 1) {
            a += __shfl_xor_sync(0xffffffffu, a, o);
            b += __shfl_xor_sync(0xffffffffu, b, o);
        }
        if (lane == 0) { g_pd2[i] = a; g_ps2[i] = b; }
    }
}

// layer-2 aggregation at mask nodes
__global__ void k_agg2() {
    int d = threadIdx.x;  // 256
    int nmask = g_nmask;
    for (int m = blockIdx.x; m < nmask; m += gridDim.x) {
        int n = g_mask_list[m];
        int ii = g_need_idx[n];
        float ps = g_ps2[ii];
        int s = g_rowptr[n], e = g_rowptr[n + 1];
        float acc = 0.f, ws = 0.f;
        for (int j = s; j < e; j++) {
            int e1 = g_csr_e1[j];
            int t = g_csr_t[j];
            int i1 = g_need_idx[e1];
            float z = ps + g_pd2[i1] + g_pr2[t];
            float w = expf(lrelu_neg(z));
            ws += w;
            if (d < D2) acc += w * (g_l2[(size_t)i1 * 400 + d] + g_rp2[(size_t)t * D2 + d]);
        }
        if (d < D2) {
            float h = (g_l2[(size_t)ii * 400 + 200 + d] * ws + acc) / (ws + 1e-12f);
            g_x2[(size_t)ii * D2 + d] = (h > 0.f) ? h : expm1f(h);
        }
    }
}

// warp-per-node: out[n] = l2norm(eu[n] + mask*x2[n]); eu = g_big cols 200-399
__global__ void k_out(float* __restrict__ out) {
    int w = (blockIdx.x * blockDim.x + threadIdx.x) >> 5;
    int lane = threadIdx.x & 31;
    if (w >= NND) return;
    int n = w;
    int msk = g_mask[n];
    int ii = msk ? g_need_idx[n] : 0;
    const float* eur = g_big + (size_t)n * 400 + 200;
    const float* x2r = g_x2 + (size_t)ii * D2;
    float vals[7];
    float ss = 0.f;
#pragma unroll
    for (int r = 0; r < 7; r++) {
        int kk = lane + r * 32;
        float v = 0.f;
        if (kk < D2) {
            v = eur[kk];
            if (msk) v += x2r[kk];
        }
        vals[r] = v;
        ss += v * v;
    }
    for (int o = 16; o > 0; o >>= 1) ss += __shfl_xor_sync(0xffffffffu, ss, o);
    float scale = 1.f / fmaxf(sqrtf(ss), 1e-12f);
    float* dst = out + (size_t)n * D2;
#pragma unroll
    for (int r = 0; r < 7; r++) {
        int kk = lane + r * 32;
        if (kk < D2) dst[kk] = vals[r] * scale;
    }
}

// his broadcast, float4
__global__ void k_his(float* __restrict__ out) {
    const size_t TOT4 = (size_t)BATCH * BATCH * (HD / 4);
    const size_t OFF4 = ((size_t)NND * D2) / 4;
    const float4* he4 = (const float4*)g_he;
    float4* o4 = (float4*)out;
    size_t idx = (size_t)blockIdx.x * blockDim.x + threadIdx.x;
    size_t stride = (size_t)gridDim.x * blockDim.x;
    for (size_t j = idx; j < TOT4; j += stride) {
        int c = (int)(j % (HD / 4));
        int b1 = (int)(j / ((size_t)BATCH * (HD / 4)));
        o4[OFF4 + j] = he4[b1 * (HD / 4) + c];
    }
}

// ---------------- launcher ----------------
extern "C" void kernel_launch(void* const* d_in, const int* in_sizes, int n_in,
                              void* d_out, int out_size) {
    const float* x     = (const float*)d_in[0];
    const float* rel   = (const float*)d_in[1];
    const float* wt2   = (const float*)d_in[2];
    const float* bt2   = (const float*)d_in[3];
    const float* W_ent = (const float*)d_in[4];
    const float* a_h   = (const float*)d_in[5];
    const float* a2_h  = (const float*)d_in[6];
    const float* W_rel = (const float*)d_in[7];
    const float* a_o   = (const float*)d_in[8];
    const float* a2_o  = (const float*)d_in[9];
    const int* el      = (const int*)d_in[10];
    const int* et      = (const int*)d_in[11];
    const int* bi      = (const int*)d_in[12];
    float* out = (float*)d_out;
    (void)in_sizes; (void)n_in; (void)out_size;

    // true device addresses for symbols passed as kernel args
    void* p;
    cudaGetSymbolAddress(&p, g_Bp1);   float* d_Bp1  = (float*)p;
    cudaGetSymbolAddress(&p, g_Bp2);   float* d_Bp2  = (float*)p;
    cudaGetSymbolAddress(&p, g_Bp3);   float* d_Bp3  = (float*)p;
    cudaGetSymbolAddress(&p, g_Bp4);   float* d_Bp4  = (float*)p;
    cudaGetSymbolAddress(&p, g_relC);  float* d_relC = (float*)p;
    cudaGetSymbolAddress(&p, g_RT2g);  float* d_RT2g = (float*)p;
    cudaGetSymbolAddress(&p, g_rp2);   float* d_rp2  = (float*)p;
    cudaGetSymbolAddress(&p, g_big);   float* d_big  = (float*)p;
    cudaGetSymbolAddress(&p, g_xg);    float* d_xg   = (float*)p;
    cudaGetSymbolAddress(&p, g_xs1);   float* d_xs1  = (float*)p;
    cudaGetSymbolAddress(&p, g_x1);    float* d_x1   = (float*)p;
    cudaGetSymbolAddress(&p, g_l2);    float* d_l2   = (float*)p;
    cudaGetSymbolAddress(&p, g_invn);  float* d_invn = (float*)p;
    cudaGetSymbolAddress(&p, g_nneed); const int* d_nneed = (const int*)p;

    const int GM = (NND + 159) / 160;  // 313

    // 1-5: setup (big GEMM is launch #6 so ncu -s5 -c1 profiles it)
    k_clear<<<256, 256>>>();
    k_mask<<<1, 512>>>(bi);
    k_pre_small<<<BATCH + 4, 256>>>(bi, wt2, bt2, et, a_h, a2_h, a_o, a2_o);
    k_pack<<<256, 256>>>(a_h, W_rel, W_ent, a_o);
    k_xnvecs<<<(NND * 32 + 127) / 128, 128>>>(x);

    // 6: merged node GEMM -> g_big[n,400] = [xd1 h0 | xd1 h1 | eu*invn]
    k_gemm<1><<<dim3(GM, 5), 256>>>(x, FINN, d_Bp2, 100, d_big, 400,
                                    nullptr, NND, FINN, 400, d_invn);

    // CSR + compaction
    k_hist_flags<<<(EE + 255) / 256, 256>>>(el);
    k_compact<<<(NND + 255) / 256, 256>>>();
    k_scan<<<1, 1024>>>();
    k_scatter<<<(EE + 255) / 256, 256>>>(el, et);

    // rel-side: relC = rel @ Bp1^T  (rp1 h0 | rp1 h1 | RT2)
    k_gemm<0><<<dim3(2, 5), 256>>>(rel, 100, d_Bp1, 100, d_relC, 400,
                                   nullptr, NREL, 100, 400, nullptr);
    k_misc1<<<207, 256>>>(rel);
    // rp2 = RT2g @ a_rel2^T
    k_gemm<0><<<dim3(2, 3), 256>>>(d_RT2g, D2, a_o + 400, 600, d_rp2, D2,
                                   nullptr, NREL, D2, D2, nullptr);
    k_pr2<<<25, 256>>>();

    // compact node work
    k_gather_xg<<<512, 256>>>(x);
    k_gemm<0><<<dim3(GM, 3), 256>>>(d_xg, FINN, d_Bp3, 100, d_xs1, D2,
                                    d_nneed, 0, FINN, D2, nullptr);
    k_agg1<<<8192, 128>>>();
    // merged layer-2 GEMM: g_l2[i,400] = [xd2 | xs2]
    k_gemm<0><<<dim3(GM, 5), 256>>>(d_x1, D2, d_Bp4, D2, d_l2, 400,
                                    d_nneed, 0, D2, 400, nullptr);
    k_pdps<<<512, 256>>>();
    k_agg2<<<512, 256>>>();

    // outputs
    k_out<<<(NND * 32 + 255) / 256, 256>>>(out);
    k_his<<<2048, 256>>>(out);
}